// round 17
// baseline (speedup 1.0000x reference)
#include <cuda_runtime.h>
#include <cuda_bf16.h>
#include <cstdint>

// ===========================================================================
// LossRecovery, Gram formulation, temporal Gram eliminated algebraically:
//   E  = Wq G Wk^T + rank-1,  G = X^T X (symmetric)
//   X1 = X + gs*(X M1^T + 1 mb^T)   [gs = s_gamma!]
//   H  = K0 + gs*M1*K0 + gs*mb*sx^T,  K0 = X^T Xsigma  (side stream, early)
//   E2 = A2*(K0 Wk'^T) + gs*(Wq' mb) (x) ut + rank-1,  A2 = Wq'(I + gs*M1)
//   out1 = X*(attn*Wv)^T + attn*bv
// ===========================================================================

__device__ uint32_t g_xh[65536L * 128];                               // x hi, s-major
__device__ uint32_t g_xth[16L * 256 * 2048], g_xtl[16L * 256 * 2048]; // x^T planes
__device__ uint32_t g_xsh[16L * 256 * 2048], g_xsl[16L * 256 * 2048]; // x^T sigma-perm
__device__ uint32_t g_wh[6 * 32768], g_wl[6 * 32768];
__device__ uint32_t g_wvth[32768];                                    // sv_w^T hi
__device__ uint32_t g_vh[16L * 4096 * 128];
__device__ uint32_t g_M1h[16L * 256 * 128], g_M1Th[16L * 256 * 128];
__device__ float    g_attnP[64L * 65536];
__device__ float    g_attnP2[64L * 65536];
__device__ uint32_t g_attnB[16L * 256 * 128];
__device__ uint32_t g_Gh[16L * 256 * 128], g_Gl[16L * 256 * 128];
__device__ uint32_t g_K0h[16L * 256 * 128], g_K0l[16L * 256 * 128];
__device__ uint32_t g_PTh[16L * 256 * 128], g_PTl[16L * 256 * 128];
__device__ uint32_t g_PT0h[16L * 256 * 128], g_PT0l[16L * 256 * 128];
__device__ uint32_t g_A2h[16L * 256 * 128], g_A2l[16L * 256 * 128];
__device__ float    g_sxP[32 * 4096];
__device__ float    g_mb[4096], g_wqmb[4096], g_sxv[4096];
__device__ float    g_us[4096], g_vs[4096], g_ut[4096], g_vt[4096];

#define CP16(dst, src) asm volatile("cp.async.cg.shared.global [%0], [%1], 16;\n" :: "r"(dst), "l"(src))
#define CPCOMMIT()     asm volatile("cp.async.commit_group;\n" ::: "memory")
#define CPWAIT(n)      asm volatile("cp.async.wait_group %0;\n" :: "n"(n) : "memory")

#define LDSM4(d0, d1, d2, d3, a) \
    asm volatile("ldmatrix.sync.aligned.m8n8.x4.shared.b16 {%0,%1,%2,%3}, [%4];" \
        : "=r"(d0), "=r"(d1), "=r"(d2), "=r"(d3) : "r"(a))

__device__ __forceinline__ uint32_t pack_hi(float v0, float v1) {
    uint32_t h;
    asm("cvt.rn.bf16x2.f32 %0, %1, %2;" : "=r"(h) : "f"(v1), "f"(v0));
    return h;  // lo half = v0
}
__device__ __forceinline__ void pack_pair(float v0, float v1, uint32_t& h, uint32_t& l) {
    h = pack_hi(v0, v1);
    const float h0 = __uint_as_float(h << 16);
    const float h1 = __uint_as_float(h & 0xFFFF0000u);
    l = pack_hi(v0 - h0, v1 - h1);
}

#define MMA_BF16(ac, a0, a1, a2, a3, b0, b1) \
    asm volatile("mma.sync.aligned.m16n8k16.row.col.f32.bf16.bf16.f32 " \
        "{%0,%1,%2,%3},{%4,%5,%6,%7},{%8,%9},{%0,%1,%2,%3};" \
        : "+f"((ac)[0]), "+f"((ac)[1]), "+f"((ac)[2]), "+f"((ac)[3]) \
        : "r"(a0), "r"(a1), "r"(a2), "r"(a3), "r"(b0), "r"(b1))

// ---------------------------------------------------------------------------
// NT GEMM over packed-bf16 planes. NPASS: 1 = AhBh; 3 = +AhBl+AlBh.
//  AMODE 0 plain | 2 v2-gather.
//  EMODE 0 hi-plane+bias | 2 fp32 scores | 3 gamma*(acc+bias?)+res
//        | 4 transposed pair planes | 5 z-batched hi plane
//        | 6 row-major hi + transposed hi (M1 / M1^T)
//        | 7 pair planes = gamma*acc + res (A2 assembly)
//  SYMM: skip block (1,0).
template <int NPASS, int BPL, int AMODE, int EMODE, bool SYMM>
__global__ __launch_bounds__(256, 2) void gemm(
    const uint32_t* __restrict__ aH, const uint32_t* __restrict__ aL, int aW, long aZ,
    const uint32_t* __restrict__ bH, const uint32_t* __restrict__ bL, int bW, long bZ,
    int KdimW,
    const float* __restrict__ bias, const float* __restrict__ gammaPtr,
    const float* __restrict__ res, int ldr,
    float* __restrict__ outF, uint32_t* __restrict__ outH, uint32_t* __restrict__ outL)
{
    if (SYMM && blockIdx.x == 1 && blockIdx.y == 0) return;

    extern __shared__ uint32_t sm[];
    constexpr int ALD = 20;
    constexpr int APL = (NPASS >= 2) ? 2 : 1;
    constexpr int STAGEW = (APL * 128 + BPL * 128) * ALD;
    constexpr int NSTAGE = (STAGEW > 8192) ? 2 : 3;
    const uint32_t sbB = (uint32_t)__cvta_generic_to_shared(sm);

    const int tid = threadIdx.x;
    const int wid = tid >> 5, lane = tid & 31;
    const int grp = lane >> 2, tig = lane & 3;
    const int row0 = blockIdx.x * 128, col0 = blockIdx.y * 128;
    const int z = blockIdx.z;
    int zA = z;
    long koffW = 0;
    if (EMODE == 2) { zA = z & 15; koffW = (long)(z >> 4) * KdimW; }

    constexpr int MI = 4;
    const int m_base = (wid >> 2) * 64;
    const int n_base = (wid & 3) * 32;

    float acc[MI][4][4];
#pragma unroll
    for (int mi = 0; mi < MI; mi++)
#pragma unroll
        for (int ni = 0; ni < 4; ni++)
#pragma unroll
            for (int e = 0; e < 4; e++) acc[mi][ni][e] = 0.f;

    const int ar = tid >> 1, hw = (tid & 1) * 8;
    long arow;
    long astep = 16;
    if (AMODE == 0) {
        arow = (long)zA * aZ + (long)(row0 + ar) * aW + koffW + hw;
    } else {  // v2 gather
        const int bq = z >> 3, chHi = z & 7;
        arow = ((long)(bq * 8) * 4096 + (row0 + ar)) * 128 + chHi * 16 + hw;
        astep = 4096L * 128;
    }
    const int bn = tid >> 1, hwB = (tid & 1) * 8;
    const long brow = (long)zA * bZ + (long)(col0 + bn) * bW + koffW + hwB;

    const int nCh = KdimW >> 4;
    const uint32_t ALo = 128 * ALD;
    const uint32_t BHo = APL * 128 * ALD;
    const uint32_t BLo = BHo + 128 * ALD;

    auto load_tile = [&](int kc, int s) {
        const long ka = arow + (long)kc * astep;
        const long kb = brow + (long)kc * 16;
        const uint32_t aD = sbB + (uint32_t)(s * STAGEW + ar * ALD + hw) * 4u;
        CP16(aD, aH + ka); CP16(aD + 16u, aH + ka + 4);
        if (APL == 2) {
            const uint32_t aD2 = aD + ALo * 4u;
            CP16(aD2, aL + ka); CP16(aD2 + 16u, aL + ka + 4);
        }
        const uint32_t bD = sbB + (uint32_t)(s * STAGEW + BHo + bn * ALD + hwB) * 4u;
        CP16(bD, bH + kb); CP16(bD + 16u, bH + kb + 4);
        if (BPL == 2) {
            const uint32_t bD2 = sbB + (uint32_t)(s * STAGEW + BLo + bn * ALD + hwB) * 4u;
            CP16(bD2, bL + kb); CP16(bD2 + 16u, bL + kb + 4);
        }
    };

    const int la7 = lane & 7, lg = lane >> 3;
    const uint32_t aoff = (uint32_t)(((m_base + la7 + ((lg & 1) << 3)) * ALD
                                      + ((lg >> 1) << 2)) * 4);
    const uint32_t boff = (uint32_t)(((n_base + la7 + ((lg >> 1) << 3)) * ALD
                                      + ((lg & 1) << 2)) * 4);

    auto compute = [&](int s) {
        const uint32_t stB = sbB + (uint32_t)(s * STAGEW) * 4u;
#pragma unroll
        for (int ks = 0; ks < 2; ks++) {
            const uint32_t kby = (uint32_t)(ks * 32);
            uint32_t bh[4][2], bl[4][2];
#pragma unroll
            for (int p = 0; p < 2; p++) {
                const uint32_t ba = stB + BHo * 4u + boff + (uint32_t)(p * 16 * ALD * 4) + kby;
                LDSM4(bh[2 * p][0], bh[2 * p][1], bh[2 * p + 1][0], bh[2 * p + 1][1], ba);
                if (BPL == 2) {
                    const uint32_t ba2 = stB + BLo * 4u + boff + (uint32_t)(p * 16 * ALD * 4) + kby;
                    LDSM4(bl[2 * p][0], bl[2 * p][1], bl[2 * p + 1][0], bl[2 * p + 1][1], ba2);
                }
            }
#pragma unroll
            for (int mi = 0; mi < MI; mi++) {
                const uint32_t aa = stB + aoff + (uint32_t)(mi * 16 * ALD * 4) + kby;
                uint32_t ah0, ah1, ah2, ah3;
                LDSM4(ah0, ah1, ah2, ah3, aa);
#pragma unroll
                for (int ni = 0; ni < 4; ni++)
                    MMA_BF16(acc[mi][ni], ah0, ah1, ah2, ah3, bh[ni][0], bh[ni][1]);
                if (NPASS == 3) {
#pragma unroll
                    for (int ni = 0; ni < 4; ni++)
                        MMA_BF16(acc[mi][ni], ah0, ah1, ah2, ah3, bl[ni][0], bl[ni][1]);
                }
                if (NPASS >= 2) {
                    uint32_t al0, al1, al2, al3;
                    LDSM4(al0, al1, al2, al3, aa + ALo * 4u);
#pragma unroll
                    for (int ni = 0; ni < 4; ni++)
                        MMA_BF16(acc[mi][ni], al0, al1, al2, al3, bh[ni][0], bh[ni][1]);
                }
            }
        }
    };

    load_tile(0, 0); CPCOMMIT();
    if (nCh > 1) load_tile(1, 1);
    CPCOMMIT();
    if (NSTAGE == 2) {
        for (int kc = 0; kc < nCh; kc++) {
            CPWAIT(1);
            __syncthreads();
            compute(kc & 1);
            __syncthreads();
            if (kc + 2 < nCh) { load_tile(kc + 2, kc & 1); CPCOMMIT(); }
        }
    } else {
        for (int kc = 0; kc < nCh; kc++) {
            CPWAIT(1);
            __syncthreads();
            const int ld = kc + 2;
            if (ld < nCh) load_tile(ld, ld % 3);
            CPCOMMIT();
            compute(kc % 3);
        }
    }

    // ---- epilogues ----
    if (EMODE == 4 || EMODE == 6) {
        if (EMODE == 6) {
            // row-major hi planes straight from acc
#pragma unroll
            for (int mi = 0; mi < MI; mi++)
#pragma unroll
                for (int ni = 0; ni < 4; ni++) {
                    const int r0g = m_base + mi * 16 + grp;
                    const int cb = n_base + ni * 8 + 2 * tig;
                    const int c = col0 + cb;
#pragma unroll
                    for (int half = 0; half < 2; half++) {
                        const int r = row0 + r0g + half * 8;
                        outH[((long)z * 256 + r) * 128 + (c >> 1)]
                            = pack_hi(acc[mi][ni][2 * half], acc[mi][ni][2 * half + 1]);
                    }
                }
        }
        __syncthreads();
        float* sC = (float*)sm;
#pragma unroll
        for (int mi = 0; mi < MI; mi++)
#pragma unroll
            for (int ni = 0; ni < 4; ni++) {
                const int r0 = m_base + mi * 16 + grp;
                const int cb = n_base + ni * 8 + 2 * tig;
                sC[r0 * 133 + cb] = acc[mi][ni][0];
                sC[r0 * 133 + cb + 1] = acc[mi][ni][1];
                sC[(r0 + 8) * 133 + cb] = acc[mi][ni][2];
                sC[(r0 + 8) * 133 + cb + 1] = acc[mi][ni][3];
            }
        __syncthreads();
        const int p = tid & 63, colg = tid >> 6;
        for (int cp = 0; cp < 32; cp++) {
            const int col = cp * 4 + colg;
            const long w = ((long)(z * 256 + col0 + col)) * 128 + (row0 >> 1) + p;
            if (EMODE == 4) {
                uint32_t h, l;
                pack_pair(sC[(2 * p) * 133 + col], sC[(2 * p + 1) * 133 + col], h, l);
                outH[w] = h; outL[w] = l;
            } else {
                outL[w] = pack_hi(sC[(2 * p) * 133 + col], sC[(2 * p + 1) * 133 + col]);
            }
        }
    } else if (EMODE == 7) {
        const float gamma = __ldg(gammaPtr);
#pragma unroll
        for (int mi = 0; mi < MI; mi++)
#pragma unroll
            for (int ni = 0; ni < 4; ni++) {
                const int r0g = m_base + mi * 16 + grp;
                const int cb = n_base + ni * 8 + 2 * tig;
                const int c = col0 + cb;
#pragma unroll
                for (int half = 0; half < 2; half++) {
                    const int r = row0 + r0g + half * 8;
                    const float v0 = gamma * acc[mi][ni][2 * half] + __ldg(&res[(long)r * 256 + c]);
                    const float v1 = gamma * acc[mi][ni][2 * half + 1] + __ldg(&res[(long)r * 256 + c + 1]);
                    uint32_t h, l;
                    pack_pair(v0, v1, h, l);
                    const long w = ((long)z * 256 + r) * 128 + (c >> 1);
                    outH[w] = h; outL[w] = l;
                }
            }
    } else {
        float gamma = 0.f;
        if (EMODE == 3) gamma = __ldg(gammaPtr);
#pragma unroll
        for (int mi = 0; mi < MI; mi++)
#pragma unroll
            for (int ni = 0; ni < 4; ni++) {
                const int r0g = m_base + mi * 16 + grp;
                const int cb = n_base + ni * 8 + 2 * tig;
                const int c = col0 + cb;
#pragma unroll
                for (int half = 0; half < 2; half++) {
                    const int r = row0 + r0g + half * 8;
                    float v0 = acc[mi][ni][2 * half];
                    float v1 = acc[mi][ni][2 * half + 1];
                    if (EMODE == 0) {
                        v0 += __ldg(&bias[c]);
                        v1 += __ldg(&bias[c + 1]);
                        outH[(long)r * 128 + (c >> 1)] = pack_hi(v0, v1);
                    } else if (EMODE == 5) {
                        outH[((long)z * 256 + r) * 128 + (c >> 1)] = pack_hi(v0, v1);
                    } else if (EMODE == 2) {
                        float2 st = {v0, v1};
                        *(float2*)(outF + (long)z * 65536 + (long)r * 256 + c) = st;
                    } else {
                        const long rr = (long)z * 4096 + r;
                        if (bias) {
                            v0 += __ldg(&bias[z * 256 + c]);
                            v1 += __ldg(&bias[z * 256 + c + 1]);
                        }
                        v0 = gamma * v0 + res[rr * (long)ldr + c];
                        v1 = gamma * v1 + res[rr * (long)ldr + c + 1];
                        float2 st = {v0, v1};
                        *(float2*)(outF + rr * 256 + c) = st;
                    }
                }
            }
    }
}

// ---------------- fused: x -> xh + xth/xtl planes + rowsum partials --------
__global__ __launch_bounds__(256) void prep_x(const float* __restrict__ x) {
    __shared__ float tile[128][65];
    __shared__ float colp[4][64];
    const int st = blockIdx.x, ct = blockIdx.y, z = blockIdx.z;
    const int t = threadIdx.x;
    const int col = t & 63, r4 = t >> 6;
    const long base = ((long)z * 4096 + st * 128) * 259 + ct * 64;
#pragma unroll
    for (int j = 0; j < 32; j++) {
        const int row = r4 + j * 4;
        tile[row][col] = x[base + (long)row * 259 + col];
    }
    __syncthreads();
#pragma unroll
    for (int k = 0; k < 16; k++) {
        const int idx = t + k * 256;
        const int row = idx >> 5, jw = idx & 31;
        g_xh[((long)z * 4096 + st * 128 + row) * 128 + ct * 32 + jw]
            = pack_hi(tile[row][2 * jw], tile[row][2 * jw + 1]);
    }
#pragma unroll
    for (int k = 0; k < 16; k++) {
        const int idx = t + k * 256;
        const int c = idx >> 6, p = idx & 63;
        uint32_t h, l;
        pack_pair(tile[2 * p][c], tile[2 * p + 1][c], h, l);
        const long w = ((long)z * 256 + ct * 64 + c) * 2048 + st * 64 + p;
        g_xth[w] = h; g_xtl[w] = l;
    }
    {
        float s = 0.f;
#pragma unroll 4
        for (int r = r4 * 32; r < r4 * 32 + 32; r++) s += tile[r][col];
        colp[r4][col] = s;
        __syncthreads();
        if (t < 64)
            g_sxP[(long)st * 4096 + z * 256 + ct * 64 + t]
                = colp[0][t] + colp[1][t] + colp[2][t] + colp[3][t];
    }
}

// ---------------- sigma-permuted x^T planes ---------------------------------
__global__ __launch_bounds__(256) void transpose_xs(const float* __restrict__ x) {
    __shared__ float tile[64][65];
    const int st = blockIdx.x, ct = blockIdx.y, z = blockIdx.z;
    const int t = threadIdx.x;
#pragma unroll
    for (int j = 0; j < 16; j++) {
        const int i = (t >> 6) + j * 4;
        const int col = t & 63;
        tile[i][col] = x[((long)(z * 4096 + i * 64 + st)) * 259 + ct * 64 + col];
    }
    __syncthreads();
#pragma unroll
    for (int j = 0; j < 8; j++) {
        const int cl = (t >> 5) + j * 8;
        const int wi = t & 31;
        uint32_t h, l;
        pack_pair(tile[2 * wi][cl], tile[2 * wi + 1][cl], h, l);
        const long w = ((long)(z * 256 + ct * 64 + cl)) * 2048 + st * 32 + wi;
        g_xsh[w] = h; g_xsl[w] = l;
    }
}

// ---------------- weights -> planes (+ sv^T hi plane) -----------------------
__global__ __launch_bounds__(256) void prep_w(const float* w0, const float* w1,
                                              const float* w2, const float* w3,
                                              const float* w4, const float* w5) {
    const int id = blockIdx.x * 256 + threadIdx.x;
    if (id < 6 * 32768) {
        const int m = id >> 15, rc = id & 32767;
        const float* w = (m == 0) ? w0 : (m == 1) ? w1 : (m == 2) ? w2
                       : (m == 3) ? w3 : (m == 4) ? w4 : w5;
        uint32_t h, l;
        pack_pair(w[rc * 2], w[rc * 2 + 1], h, l);
        g_wh[id] = h; g_wl[id] = l;
    } else {
        const int id2 = id - 6 * 32768;
        const int e = id2 >> 7, dw = id2 & 127;
        g_wvth[id2] = pack_hi(w2[(2 * dw) * 256 + e], w2[(2 * dw + 1) * 256 + e]);
    }
}

// ---------------- matvec with fused 32-way partial reduce (+ sx out) -------
__global__ __launch_bounds__(256) void matvec3r(const float* Wa, const float* Wb,
                                                const float* Wc,
                                                const float* __restrict__ P,
                                                float* oa, float* ob, float* oc,
                                                float* sxOut) {
    __shared__ float sx[256];
    const int z = blockIdx.x, d = threadIdx.x, m = blockIdx.y;
    float s0 = 0.f;
#pragma unroll 8
    for (int j = 0; j < 32; j++) s0 += P[(long)j * 4096 + z * 256 + d];
    sx[d] = s0;
    if (m == 0) sxOut[z * 256 + d] = s0;
    __syncthreads();
    const float* W = (m == 0) ? Wa : (m == 1) ? Wb : Wc;
    float* o = (m == 0) ? oa : (m == 1) ? ob : oc;
    const float* w = W + (long)d * 256;
    float s = 0.f;
    for (int c = 0; c < 256; c++) s += w[c] * sx[c];
    o[z * 256 + d] = s;
}

// ---------------- sx1 / vt / wqmb from M1, mb, sx (gamma = s_gamma!) --------
__global__ __launch_bounds__(256) void smallvec(const uint32_t* __restrict__ M1h,
                                                const float* __restrict__ sx,
                                                const float* __restrict__ mb,
                                                const float* __restrict__ tqw,
                                                const float* __restrict__ sgamma,
                                                float* __restrict__ vt,
                                                float* __restrict__ wqmb) {
    __shared__ float s1[256];
    const int z = blockIdx.x, c = threadIdx.x;
    const float g = __ldg(sgamma);
    float m1sx = 0.f;
    const uint32_t* row = M1h + ((long)z * 256 + c) * 128;
    for (int w = 0; w < 128; w++) {
        const uint32_t u = row[w];
        m1sx += __uint_as_float(u << 16) * sx[z * 256 + 2 * w]
              + __uint_as_float(u & 0xFFFF0000u) * sx[z * 256 + 2 * w + 1];
    }
    const float* tw = tqw + (long)c * 256;
    float wm = 0.f;
    for (int e = 0; e < 256; e++) wm += tw[e] * mb[z * 256 + e];
    wqmb[z * 256 + c] = wm;
    s1[c] = sx[z * 256 + c] + g * (m1sx + 4096.f * mb[z * 256 + c]);
    __syncthreads();
    float v = 0.f;
    for (int e = 0; e < 256; e++) v += tw[e] * s1[e];
    vt[z * 256 + c] = v;
}

// ---------------- sum 4 split-K partials -> packed planes (opt. mirror) ----
template <bool MIRROR>
__global__ __launch_bounds__(256) void combine_pack(const float* __restrict__ P,
                                                    uint32_t* __restrict__ gh,
                                                    uint32_t* __restrict__ gl) {
    const long i = (long)blockIdx.x * 256 + threadIdx.x;
    const int z = (int)(i >> 15);
    const int r = (int)(i & 32767);
    const int c = r >> 7, dw = r & 127;
    float v0, v1;
    if (MIRROR && c >= 128 && dw < 64) {
        const long e0 = (long)z * 65536 + (2 * dw) * 256 + c;
        const long e1 = e0 + 256;
        v0 = P[e0] + P[e0 + 1048576] + P[e0 + 2097152] + P[e0 + 3145728];
        v1 = P[e1] + P[e1 + 1048576] + P[e1 + 2097152] + P[e1 + 3145728];
    } else {
        const long e = (long)z * 65536 + c * 256 + 2 * dw;
        v0 = P[e] + P[e + 1048576] + P[e + 2097152] + P[e + 3145728];
        v1 = P[e + 1] + P[e + 1 + 1048576] + P[e + 1 + 2097152] + P[e + 1 + 3145728];
    }
    uint32_t h, l;
    pack_pair(v0, v1, h, l);
    gh[i] = h; gl[i] = l;
}

// ---------------- softmax with rank-1 terms, pack; opt mbias / wqmb --------
template <bool PERM, bool MBIAS>
__global__ __launch_bounds__(256) void softmax_rank1(
    const float* __restrict__ S, const float* __restrict__ u,
    const float* __restrict__ vvec, const float* __restrict__ bq,
    const float* __restrict__ bk, uint32_t* __restrict__ O,
    const float* __restrict__ bv, float* __restrict__ mbOut,
    const float* __restrict__ wqmbV, const float* __restrict__ gPtr)
{
    __shared__ float srow[8][256];
    const int wid = threadIdx.x >> 5, lane = threadIdx.x & 31;
    const int row = blockIdx.x * 8 + wid;
    const int z = row >> 8, c = row & 255;
    const float bqc = bq[c], vc = vvec[z * 256 + c];
    float cu = bqc;
    if (wqmbV) cu += __ldg(gPtr) * wqmbV[z * 256 + c];
    const float* p = S + (long)row * 256;
    float vv[8];
    float mx = -1e30f;
#pragma unroll
    for (int j = 0; j < 8; j++) {
        const int d = lane * 8 + j;
        const float bkd = bk[d];
        vv[j] = p[d] + cu * u[z * 256 + d] + bkd * (4096.f * bqc + vc);
        mx = fmaxf(mx, vv[j]);
    }
#pragma unroll
    for (int o = 16; o; o >>= 1) mx = fmaxf(mx, __shfl_xor_sync(0xffffffffu, mx, o));
    float s = 0.f;
#pragma unroll
    for (int j = 0; j < 8; j++) { vv[j] = __expf(vv[j] - mx); s += vv[j]; }
#pragma unroll
    for (int o = 16; o; o >>= 1) s += __shfl_xor_sync(0xffffffffu, s, o);
    const float inv = 1.f / s;
#pragma unroll
    for (int j = 0; j < 8; j++) srow[wid][lane * 8 + j] = vv[j] * inv;
    __syncwarp();
    if (MBIAS) {
        float mbv = 0.f;
#pragma unroll
        for (int j = 0; j < 8; j++) {
            const int d = lane * 8 + j;
            mbv += srow[wid][d] * __ldg(&bv[d]);
        }
#pragma unroll
        for (int o = 16; o; o >>= 1) mbv += __shfl_xor_sync(0xffffffffu, mbv, o);
        if (lane == 0) mbOut[row] = mbv;
    }
#pragma unroll
    for (int t = 0; t < 4; t++) {
        const int m = lane * 4 + t;
        int d0 = 2 * m, d1 = 2 * m + 1;
        if (PERM) {
            d0 = ((d0 & 31) << 3) | (d0 >> 5);
            d1 = ((d1 & 31) << 3) | (d1 >> 5);
        }
        O[(long)row * 128 + m] = pack_hi(srow[wid][d0], srow[wid][d1]);
    }
}

// ---------------- launch ----------------------------------------------------
extern "C" void kernel_launch(void* const* d_in, const int* in_sizes, int n_in,
                              void* d_out, int out_size)
{
    const float* x    = (const float*)d_in[0];
    const float* sq_w = (const float*)d_in[3];
    const float* sq_b = (const float*)d_in[4];
    const float* sk_w = (const float*)d_in[5];
    const float* sk_b = (const float*)d_in[6];
    const float* sv_w = (const float*)d_in[7];
    const float* sv_b = (const float*)d_in[8];
    const float* tq_w = (const float*)d_in[9];
    const float* tq_b = (const float*)d_in[10];
    const float* tk_w = (const float*)d_in[11];
    const float* tk_b = (const float*)d_in[12];
    const float* tv_w = (const float*)d_in[13];
    const float* tv_b = (const float*)d_in[14];
    const float* s_gamma = (const float*)d_in[15];
    const float* t_gamma = (const float*)d_in[16];
    float* out = (float*)d_out;

    uint32_t *xh, *xth, *xtl, *xsh, *xsl, *wh, *wl, *wvth;
    uint32_t *vh, *M1h, *M1Th, *attnB, *Gh, *Gl, *K0h, *K0l;
    uint32_t *PTh, *PTl, *PT0h, *PT0l, *A2h, *A2l;
    float *attnP, *attnP2, *sxP, *mb, *wqmb, *sxv, *us, *vs, *ut, *vt;
    cudaGetSymbolAddress((void**)&xh, g_xh);
    cudaGetSymbolAddress((void**)&xth, g_xth);   cudaGetSymbolAddress((void**)&xtl, g_xtl);
    cudaGetSymbolAddress((void**)&xsh, g_xsh);   cudaGetSymbolAddress((void**)&xsl, g_xsl);
    cudaGetSymbolAddress((void**)&wh, g_wh);     cudaGetSymbolAddress((void**)&wl, g_wl);
    cudaGetSymbolAddress((void**)&wvth, g_wvth);
    cudaGetSymbolAddress((void**)&vh, g_vh);
    cudaGetSymbolAddress((void**)&M1h, g_M1h);   cudaGetSymbolAddress((void**)&M1Th, g_M1Th);
    cudaGetSymbolAddress((void**)&attnP, g_attnP);
    cudaGetSymbolAddress((void**)&attnP2, g_attnP2);
    cudaGetSymbolAddress((void**)&attnB, g_attnB);
    cudaGetSymbolAddress((void**)&Gh, g_Gh);     cudaGetSymbolAddress((void**)&Gl, g_Gl);
    cudaGetSymbolAddress((void**)&K0h, g_K0h);   cudaGetSymbolAddress((void**)&K0l, g_K0l);
    cudaGetSymbolAddress((void**)&PTh, g_PTh);   cudaGetSymbolAddress((void**)&PTl, g_PTl);
    cudaGetSymbolAddress((void**)&PT0h, g_PT0h); cudaGetSymbolAddress((void**)&PT0l, g_PT0l);
    cudaGetSymbolAddress((void**)&A2h, g_A2h);   cudaGetSymbolAddress((void**)&A2l, g_A2l);
    cudaGetSymbolAddress((void**)&sxP, g_sxP);
    cudaGetSymbolAddress((void**)&mb, g_mb);     cudaGetSymbolAddress((void**)&wqmb, g_wqmb);
    cudaGetSymbolAddress((void**)&sxv, g_sxv);
    cudaGetSymbolAddress((void**)&us, g_us);     cudaGetSymbolAddress((void**)&vs, g_vs);
    cudaGetSymbolAddress((void**)&ut, g_ut);     cudaGetSymbolAddress((void**)&vt, g_vt);

    auto convV = gemm<1, 1, 0, 0, false>;   // tv conv
    auto bigG  = gemm<3, 2, 0, 2, true>;    // G (symmetric, split-K=4)
    auto bigS  = gemm<3, 2, 0, 2, false>;   // K0 (split-K) and S / S2 GEMMs
    auto Pk    = gemm<3, 2, 0, 4, false>;   // planes * Wk^T -> P^T pair planes
    auto m1k   = gemm<1, 1, 0, 6, false>;   // M1 + M1^T hi planes
    auto A2k   = gemm<1, 1, 0, 7, false>;   // A2 = s_gamma*(Wq' M1) + Wq'
    auto outV1 = gemm<1, 1, 0, 3, false>;   // spatial out (X*M1^T + mb)
    auto outV2 = gemm<1, 1, 2, 3, false>;   // temporal out (v2 gather)

    const int SMC = 3 * (128 + 128) * 20 * 4;      // 61440
    const int SMG = 2 * (256 + 256) * 20 * 4;      // 81920
    const int SMO = 70656;                         // m1k (sC staging)
    cudaFuncSetAttribute(convV, cudaFuncAttributeMaxDynamicSharedMemorySize, SMC);
    cudaFuncSetAttribute(bigG,  cudaFuncAttributeMaxDynamicSharedMemorySize, SMG);
    cudaFuncSetAttribute(bigS,  cudaFuncAttributeMaxDynamicSharedMemorySize, SMG);
    cudaFuncSetAttribute(Pk,    cudaFuncAttributeMaxDynamicSharedMemorySize, SMG);
    cudaFuncSetAttribute(m1k,   cudaFuncAttributeMaxDynamicSharedMemorySize, SMO);
    cudaFuncSetAttribute(A2k,   cudaFuncAttributeMaxDynamicSharedMemorySize, SMC);
    cudaFuncSetAttribute(outV1, cudaFuncAttributeMaxDynamicSharedMemorySize, SMC);
    cudaFuncSetAttribute(outV2, cudaFuncAttributeMaxDynamicSharedMemorySize, SMC);

    const dim3 px(32, 4, 16);
    const dim3 ts(64, 4, 16);
    const dim3 cg(512, 2, 1);
    const dim3 gg(2, 2, 64);
    const dim3 pg(2, 2, 16);
    const dim3 og(32, 2, 16);

    cudaStream_t side;
    cudaStreamCreateWithFlags(&side, cudaStreamNonBlocking);
    cudaEvent_t e1, eM, e4;
    cudaEventCreateWithFlags(&e1, cudaEventDisableTiming);
    cudaEventCreateWithFlags(&eM, cudaEventDisableTiming);
    cudaEventCreateWithFlags(&e4, cudaEventDisableTiming);

    prep_x<<<px, 256>>>(x);
    prep_w<<<896, 256>>>(sq_w, sk_w, sv_w, tq_w, tk_w, tv_w);
    matvec3r<<<dim3(16, 3), 256>>>(sk_w, sq_w, tk_w, sxP, us, vs, ut, sxv);

    // ---- side: K0 chain + tv conv, hidden under spatial chain ----
    cudaEventRecord(e1, 0);
    cudaStreamWaitEvent(side, e1, 0);
    transpose_xs<<<ts, 256, 0, side>>>(x);
    bigS<<<gg, 256, SMG, side>>>(xth, xtl, 2048, 524288L, xsh, xsl, 2048, 524288L, 512,
                                 nullptr, nullptr, nullptr, 0, attnP2, nullptr, nullptr);
    combine_pack<false><<<2048, 256, 0, side>>>(attnP2, K0h, K0l);
    Pk<<<pg, 256, SMG, side>>>(K0h, K0l, 128, 32768L, wh + 4 * 32768, wl + 4 * 32768, 128, 0, 128,
                               nullptr, nullptr, nullptr, 0, nullptr, PT0h, PT0l);
    convV<<<cg, 256, SMC, side>>>(xh, nullptr, 128, 0, wh + 5 * 32768, nullptr, 128, 0, 128,
                                  tv_b, nullptr, nullptr, 0, nullptr, vh, nullptr);

    // ---- main: spatial chain ----
    bigG<<<gg, 256, SMG>>>(xth, xtl, 2048, 524288L, xth, xtl, 2048, 524288L, 512,
                           nullptr, nullptr, nullptr, 0, attnP, nullptr, nullptr);
    combine_pack<true><<<2048, 256>>>(attnP, Gh, Gl);
    Pk<<<pg, 256, SMG>>>(Gh, Gl, 128, 32768L, wh + 1 * 32768, wl + 1 * 32768, 128, 0, 128,
                         nullptr, nullptr, nullptr, 0, nullptr, PTh, PTl);
    bigS<<<pg, 256, SMG>>>(wh + 0 * 32768, wl + 0 * 32768, 128, 0, PTh, PTl, 128, 32768L, 128,
                           nullptr, nullptr, nullptr, 0, attnP, nullptr, nullptr);
    softmax_rank1<false, true><<<512, 256>>>(attnP, us, vs, sq_b, sk_b, attnB, sv_b, mb,
                                             nullptr, nullptr);
    m1k<<<pg, 256, SMO>>>(attnB, nullptr, 128, 32768L, wvth, nullptr, 128, 0, 128,
                          nullptr, nullptr, nullptr, 0, nullptr, M1h, M1Th);
    cudaEventRecord(eM, 0);

    // ---- side: temporal score chain (concurrent with outV1) ----
    // NOTE: all X1-expansion gammas are s_gamma (x1 = s_gamma*out + x).
    cudaStreamWaitEvent(side, eM, 0);
    A2k<<<pg, 256, SMC, side>>>(wh + 3 * 32768, nullptr, 128, 0, M1Th, nullptr, 128, 32768L, 128,
                                nullptr, s_gamma, tq_w, 256, nullptr, A2h, A2l);
    smallvec<<<16, 256, 0, side>>>(M1h, sxv, mb, tq_w, s_gamma, vt, wqmb);
    bigS<<<pg, 256, SMG, side>>>(A2h, A2l, 128, 32768L, PT0h, PT0l, 128, 32768L, 128,
                                 nullptr, nullptr, nullptr, 0, attnP, nullptr, nullptr);
    softmax_rank1<true, false><<<512, 256, 0, side>>>(attnP, ut, vt, tq_b, tk_b, attnB,
                                                      nullptr, nullptr, wqmb, s_gamma);
    cudaEventRecord(e4, side);

    // ---- main: outputs ----
    outV1<<<og, 256, SMC>>>(xh, nullptr, 128, 524288L, M1h, nullptr, 128, 32768L, 128,
                            mb, s_gamma, x, 259, out, nullptr, nullptr);
    cudaStreamWaitEvent(0, e4, 0);
    outV2<<<og, 256, SMC>>>(vh, nullptr, 128, 0, attnB, nullptr, 128, 32768L, 128,
                            nullptr, t_gamma, out, 256, out, nullptr, nullptr);
}